// round 6
// baseline (speedup 1.0000x reference)
#include <cuda_runtime.h>
#include <cstdint>

// Problem constants (fixed shapes in reference_code)
#define BB     1024
#define CC     20
#define NN     26
#define VDIM   128
#define NSPL   10
#define NWORDS 100000

// Scores-only kernel. One block per batch row.
// scores[b,n] = sum_v x[b,v] * O[v, tgt[b,n]]
// x[b,v] = (1/C) * sum_c ( D[knot[b], ctx[b,c], v] * x_vals[b] + W[ctx[b,c], v] )
__global__ void __launch_bounds__(256)
dmspline_scores(const float* __restrict__ x_vals,
                const int*   __restrict__ knot_ids,
                const int*   __restrict__ context_ids,
                const int*   __restrict__ target_ids,
                const float* __restrict__ D,
                const float* __restrict__ W,
                const float* __restrict__ O,
                float* __restrict__ out)
{
    __shared__ float sx[VDIM];
    __shared__ int   sctx[CC];

    const int bid = blockIdx.x;
    const int tid = threadIdx.x;

    // ---- stage context ids through shared ----
    if (tid < CC) sctx[tid] = context_ids[bid * CC + tid];
    __syncthreads();

    // ---- phase 1: x[v] for v = tid (threads 0..127) ----
    if (tid < VDIM) {
        const int   knot = knot_ids[bid];
        const float xv   = x_vals[bid];
        const float* __restrict__ Dk = D + (size_t)knot * NWORDS * VDIM;
        float acc = 0.0f;
        #pragma unroll
        for (int c = 0; c < CC; ++c) {
            const int ctx = sctx[c];
            const float d = __ldg(Dk + (size_t)ctx * VDIM + tid);
            const float w = __ldg(W  + (size_t)ctx * VDIM + tid);
            acc = fmaf(d, xv, acc) + w;
        }
        sx[tid] = acc * (1.0f / CC);
    }
    __syncthreads();

    // ---- phase 2: 8 warps; warp w handles n = w, w+8, ... ----
    const int warp = tid >> 5;
    const int lane = tid & 31;
    for (int n = warp; n < NN; n += 8) {
        const int id = target_ids[bid * NN + n];
        const float* __restrict__ Ocol = O + id;  // O[v*NWORDS + id]
        float s = 0.0f;
        #pragma unroll
        for (int k = 0; k < 4; ++k) {
            const int v = lane + 32 * k;
            s = fmaf(sx[v], __ldg(Ocol + (size_t)v * NWORDS), s);
        }
        #pragma unroll
        for (int off = 16; off; off >>= 1)
            s += __shfl_down_sync(0xffffffffu, s, off);
        if (lane == 0) out[bid * NN + n] = s;
    }
}

extern "C" void kernel_launch(void* const* d_in, const int* in_sizes, int n_in,
                              void* d_out, int out_size)
{
    const float* x_vals      = (const float*)d_in[0];
    const int*   knot_ids    = (const int*)  d_in[1];
    const int*   context_ids = (const int*)  d_in[2];
    const int*   target_ids  = (const int*)  d_in[3];
    const float* D           = (const float*)d_in[4];
    const float* W           = (const float*)d_in[5];
    const float* O           = (const float*)d_in[6];
    float*       out         = (float*)d_out;

    // Lazily-created side stream + fork/join events. Created on the first
    // (uncaptured) correctness call; reused across all calls so the captured
    // graph structure is identical every time. No device memory is allocated.
    static cudaStream_t s2      = nullptr;
    static cudaEvent_t  ev_fork = nullptr;
    static cudaEvent_t  ev_join = nullptr;
    if (s2 == nullptr) {
        cudaStreamCreateWithFlags(&s2, cudaStreamNonBlocking);
        cudaEventCreateWithFlags(&ev_fork, cudaEventDisableTiming);
        cudaEventCreateWithFlags(&ev_join, cudaEventDisableTiming);
    }

    const long long dElems = (long long)NSPL * NWORDS * VDIM;
    const long long need   = (long long)BB * NN + dElems;
    const bool do_copy = ((long long)out_size >= need);

    if (do_copy) {
        // Fork: run the 512 MB D pass-through copy concurrently with the
        // scores kernel. Disjoint writes (out[0:BB*NN] vs out[BB*NN:]);
        // both only READ D, so no hazard.
        cudaEventRecord(ev_fork, 0);
        cudaStreamWaitEvent(s2, ev_fork, 0);
        cudaMemcpyAsync(out + (size_t)BB * NN, D,
                        (size_t)dElems * sizeof(float),
                        cudaMemcpyDeviceToDevice, s2);
        cudaEventRecord(ev_join, s2);
    }

    // Scores kernel on the captured (main) stream, overlapping the copy.
    dmspline_scores<<<BB, 256>>>(x_vals, knot_ids, context_ids, target_ids,
                                 D, W, O, out);

    if (do_copy) {
        // Join: main stream completes only after the copy finishes.
        cudaStreamWaitEvent(0, ev_join, 0);
    }
}

// round 8
// speedup vs baseline: 1.0025x; 1.0025x over previous
#include <cuda_runtime.h>
#include <cstdint>

// Problem constants (fixed shapes in reference_code)
#define BB     1024
#define CC     20
#define NN     26
#define VDIM   128
#define NSPL   10
#define NWORDS 100000

// Scores-only kernel. One block per batch row.
// scores[b,n] = sum_v x[b,v] * O[v, tgt[b,n]]
// x[b,v] = (1/C) * sum_c ( D[knot[b], ctx[b,c], v] * x_vals[b] + W[ctx[b,c], v] )
__global__ void __launch_bounds__(256)
dmspline_scores(const float* __restrict__ x_vals,
                const int*   __restrict__ knot_ids,
                const int*   __restrict__ context_ids,
                const int*   __restrict__ target_ids,
                const float* __restrict__ D,
                const float* __restrict__ W,
                const float* __restrict__ O,
                float* __restrict__ out)
{
    __shared__ float sx[VDIM];
    __shared__ int   sctx[CC];

    const int bid = blockIdx.x;
    const int tid = threadIdx.x;

    // ---- stage context ids through shared ----
    if (tid < CC) sctx[tid] = context_ids[bid * CC + tid];
    __syncthreads();

    // ---- phase 1: x[v] for v = tid (threads 0..127) ----
    if (tid < VDIM) {
        const int   knot = knot_ids[bid];
        const float xv   = x_vals[bid];
        const float* __restrict__ Dk = D + (size_t)knot * NWORDS * VDIM;
        float acc = 0.0f;
        #pragma unroll
        for (int c = 0; c < CC; ++c) {
            const int ctx = sctx[c];
            const float d = __ldg(Dk + (size_t)ctx * VDIM + tid);
            const float w = __ldg(W  + (size_t)ctx * VDIM + tid);
            acc = fmaf(d, xv, acc) + w;
        }
        sx[tid] = acc * (1.0f / CC);
    }
    __syncthreads();

    // ---- phase 2: warp w handles n = w, w+8, w+16, w+24 (<= 4 each).
    // All O-gather loads for ALL assigned n are issued before any reduction:
    // up to 16 independent loads in flight per thread (MLP=16 vs 4 before).
    const int warp = tid >> 5;
    const int lane = tid & 31;

    int nlist[4];
    int cnt = 0;
    #pragma unroll
    for (int n = warp; n < NN; n += 8) nlist[cnt++] = n;

    const float* __restrict__ ocol[4];
    #pragma unroll
    for (int i = 0; i < 4; ++i) {
        if (i < cnt) ocol[i] = O + target_ids[bid * NN + nlist[i]];
    }

    // Batch all gathers (front-loaded: maximum loads in flight)
    float ov[4][4];
    #pragma unroll
    for (int i = 0; i < 4; ++i) {
        if (i < cnt) {
            #pragma unroll
            for (int k = 0; k < 4; ++k) {
                ov[i][k] = __ldg(ocol[i] + (size_t)(lane + 32 * k) * NWORDS);
            }
        }
    }

    // Reduce + store
    float xs[4];
    #pragma unroll
    for (int k = 0; k < 4; ++k) xs[k] = sx[lane + 32 * k];

    #pragma unroll
    for (int i = 0; i < 4; ++i) {
        if (i < cnt) {
            float s = 0.0f;
            #pragma unroll
            for (int k = 0; k < 4; ++k) s = fmaf(xs[k], ov[i][k], s);
            #pragma unroll
            for (int off = 16; off; off >>= 1)
                s += __shfl_down_sync(0xffffffffu, s, off);
            if (lane == 0) out[bid * NN + nlist[i]] = s;
        }
    }
}

extern "C" void kernel_launch(void* const* d_in, const int* in_sizes, int n_in,
                              void* d_out, int out_size)
{
    const float* x_vals      = (const float*)d_in[0];
    const int*   knot_ids    = (const int*)  d_in[1];
    const int*   context_ids = (const int*)  d_in[2];
    const int*   target_ids  = (const int*)  d_in[3];
    const float* D           = (const float*)d_in[4];
    const float* W           = (const float*)d_in[5];
    const float* O           = (const float*)d_in[6];
    float*       out         = (float*)d_out;

    // Lazily-created LOW-PRIORITY side stream + fork/join events. Created on
    // the first (uncaptured) correctness call and reused every call, so the
    // captured graph is identical each time. No device memory is allocated.
    static cudaStream_t s2      = nullptr;
    static cudaEvent_t  ev_fork = nullptr;
    static cudaEvent_t  ev_join = nullptr;
    if (s2 == nullptr) {
        int prio_lo = 0, prio_hi = 0;
        cudaDeviceGetStreamPriorityRange(&prio_lo, &prio_hi);  // lo = least urgent
        cudaStreamCreateWithPriority(&s2, cudaStreamNonBlocking, prio_lo);
        cudaEventCreateWithFlags(&ev_fork, cudaEventDisableTiming);
        cudaEventCreateWithFlags(&ev_join, cudaEventDisableTiming);
    }

    const long long dElems = (long long)NSPL * NWORDS * VDIM;
    const long long need   = (long long)BB * NN + dElems;
    const bool do_copy = ((long long)out_size >= need);

    if (do_copy) {
        // PROPER capture fork: s2's work must descend from the origin stream's
        // capture graph (un-forked side-stream work fails capture — proven R7).
        cudaEventRecord(ev_fork, 0);
        cudaStreamWaitEvent(s2, ev_fork, 0);
        // 512 MB D pass-through on the low-priority stream: the driver's SM
        // copy kernel yields block slots to the default-priority scores kernel.
        cudaMemcpyAsync(out + (size_t)BB * NN, D,
                        (size_t)dElems * sizeof(float),
                        cudaMemcpyDeviceToDevice, s2);
        cudaEventRecord(ev_join, s2);
    }

    // Scores kernel on the captured (main, default-priority) stream.
    // Read-read on D with the copy; disjoint out regions -> no hazard.
    dmspline_scores<<<BB, 256>>>(x_vals, knot_ids, context_ids, target_ids,
                                 D, W, O, out);

    if (do_copy) {
        // Join: main stream completes only after the copy finishes.
        cudaStreamWaitEvent(0, ev_join, 0);
    }
}